// round 2
// baseline (speedup 1.0000x reference)
#include <cuda_runtime.h>
#include <cuda_bf16.h>
#include <cstdint>
#include <math.h>

#define H      256
#define E      300
#define S_SENT 1024
#define L_W    64
#define NH3    768
#define NTOPIC 100
#define NTGT   5

// ---------------- scratch (__device__ globals; no allocation allowed) ----------------
__device__ float g_dq[10 * NH3];                       // D @ q[t] table
__device__ float g_pre[S_SENT * (L_W - 1) * NH3];      // pre = Wx + Dq + b
__device__ float g_leaf[S_SENT * NH3];                 // leaf row (Wx + dq9 + b)
__device__ float g_h[S_SENT * H];                      // tree hidden / sentenceVector
__device__ float g_pA[S_SENT * NH3];                   // GEMM k-split partial 0
__device__ float g_pB[S_SENT * NH3];                   // GEMM k-split partial 1
__device__ float g_gi[S_SENT * NH3];                   // GRU input-side gates
__device__ float g_hT[H];                              // final GRU hidden

__device__ __forceinline__ float sigf(float x) { return 1.0f / (1.0f + expf(-x)); }

// ---------------- dep-type table: g_dq[t][j] = sum_k D[j][k] * q[t][k] ----------------
__global__ void prep_kernel(const float* __restrict__ D, const float* __restrict__ q) {
    __shared__ float qs[H];
    int t = blockIdx.x;                 // 0..9
    if (threadIdx.x < H) qs[threadIdx.x] = q[t * H + threadIdx.x];
    __syncthreads();
    int j = threadIdx.x;                // 768 threads
    const float* Drow = D + (size_t)j * H;
    float acc = 0.f;
#pragma unroll 8
    for (int k = 0; k < H; k++) acc += Drow[k] * qs[k];
    g_dq[t * NH3 + j] = acc;
}

// ---------------- Wx GEMM with embedding gather; epilogue builds pre / leaf ----------------
// C[m][n] = sum_e idx2vec[sidx[m]][e] * W[n][e];   m = s*64 + l
__global__ __launch_bounds__(256) void wx_kernel(
    const int* __restrict__ sidx, const int* __restrict__ dep,
    const float* __restrict__ idx2vec, const float* __restrict__ W,
    const float* __restrict__ bias) {
    __shared__ float As[10][132];
    __shared__ float Bs[10][132];
    __shared__ int   ridx[128];
    __shared__ float bsh[128];

    int tid = threadIdx.x;
    int m0 = blockIdx.y * 128, n0 = blockIdx.x * 128;
    if (tid < 128) { ridx[tid] = sidx[m0 + tid]; bsh[tid] = bias[n0 + tid]; }
    __syncthreads();

    float acc[8][8];
#pragma unroll
    for (int i = 0; i < 8; i++)
#pragma unroll
        for (int j = 0; j < 8; j++) acc[i][j] = 0.f;

    int mA = tid >> 1;             // 0..127
    int khA = (tid & 1) * 5;       // 0 or 5
    int tr = tid >> 4, tc = tid & 15;

    for (int kt = 0; kt < 30; kt++) {
        int k0 = kt * 10;
        const float* arow = idx2vec + (size_t)ridx[mA] * E + k0 + khA;
        const float* brow = W + (size_t)(n0 + mA) * E + k0 + khA;
        float av5[5], bv5[5];
#pragma unroll
        for (int u = 0; u < 5; u++) { av5[u] = arow[u]; bv5[u] = brow[u]; }
        __syncthreads();   // previous tile's reads done
#pragma unroll
        for (int u = 0; u < 5; u++) {
            As[khA + u][mA] = av5[u];
            Bs[khA + u][mA] = bv5[u];
        }
        __syncthreads();
#pragma unroll
        for (int kk = 0; kk < 10; kk++) {
            float4 a0 = *(const float4*)&As[kk][tr * 8];
            float4 a1 = *(const float4*)&As[kk][tr * 8 + 4];
            float4 b0 = *(const float4*)&Bs[kk][tc * 8];
            float4 b1 = *(const float4*)&Bs[kk][tc * 8 + 4];
            float av[8] = {a0.x, a0.y, a0.z, a0.w, a1.x, a1.y, a1.z, a1.w};
            float bv[8] = {b0.x, b0.y, b0.z, b0.w, b1.x, b1.y, b1.z, b1.w};
#pragma unroll
            for (int i = 0; i < 8; i++)
#pragma unroll
                for (int j = 0; j < 8; j++) acc[i][j] += av[i] * bv[j];
        }
    }

    // epilogue: + bias + dq[deptype];  l==63 -> leaf buffer, else pre buffer
#pragma unroll
    for (int i = 0; i < 8; i++) {
        int m = m0 + tr * 8 + i;
        int s = m >> 6, l = m & 63;
        int dj = (l == 63) ? 9 : dep[s * 63 + l];
        const float* dqrow = g_dq + dj * NH3;
        float* outr = (l == 63) ? (g_leaf + (size_t)s * NH3)
                                : (g_pre + (size_t)(s * 63 + l) * NH3);
#pragma unroll
        for (int j = 0; j < 8; j++) {
            int n = tc * 8 + j;
            outr[n0 + n] = acc[i][j] + bsh[n] + dqrow[n0 + n];
        }
    }
}

// ---------------- leaf: h = tanh(sigmoid(iu_i) * tanh(iu_u)) ----------------
__global__ void leaf_kernel() {
    int idx = blockIdx.x * 256 + threadIdx.x;   // 262144
    int s = idx >> 8, i = idx & 255;
    const float* r = g_leaf + (size_t)s * NH3;
    g_h[idx] = tanhf(sigf(r[256 + i]) * tanhf(r[512 + i]));
}

// ---------------- C_half = g_h @ B^T  (M=1024, N=768, K=256, split-K 2) ----------------
// BM=128, BN=64, BK=16, 256 threads, 8x4 microtile. grid (12, 8, 2)
__global__ __launch_bounds__(256) void ab_gemm(const float* __restrict__ B) {
    __shared__ float As[16][132];
    __shared__ float Bs[16][72];
    int tid = threadIdx.x;
    int n0 = blockIdx.x * 64, m0 = blockIdx.y * 128, kb = blockIdx.z * 128;

    float acc[8][4];
#pragma unroll
    for (int i = 0; i < 8; i++)
#pragma unroll
        for (int j = 0; j < 4; j++) acc[i][j] = 0.f;

    int mA = tid >> 1, khA = (tid & 1) * 8;
    int nB = tid >> 2, kqB = (tid & 3) * 4;
    int tr = tid >> 4, tc = tid & 15;

    for (int it = 0; it < 8; it++) {
        int k0 = kb + it * 16;
        float4 a0 = *(const float4*)(g_h + (size_t)(m0 + mA) * H + k0 + khA);
        float4 a1 = *(const float4*)(g_h + (size_t)(m0 + mA) * H + k0 + khA + 4);
        float4 b0 = *(const float4*)(B + (size_t)(n0 + nB) * H + k0 + kqB);
        __syncthreads();   // previous compute done before overwrite
        As[khA + 0][mA] = a0.x; As[khA + 1][mA] = a0.y;
        As[khA + 2][mA] = a0.z; As[khA + 3][mA] = a0.w;
        As[khA + 4][mA] = a1.x; As[khA + 5][mA] = a1.y;
        As[khA + 6][mA] = a1.z; As[khA + 7][mA] = a1.w;
        Bs[kqB + 0][nB] = b0.x; Bs[kqB + 1][nB] = b0.y;
        Bs[kqB + 2][nB] = b0.z; Bs[kqB + 3][nB] = b0.w;
        __syncthreads();
#pragma unroll
        for (int kk = 0; kk < 16; kk++) {
            float4 a0v = *(const float4*)&As[kk][tr * 8];
            float4 a1v = *(const float4*)&As[kk][tr * 8 + 4];
            float4 bv = *(const float4*)&Bs[kk][tc * 4];
            float av[8] = {a0v.x, a0v.y, a0v.z, a0v.w, a1v.x, a1v.y, a1v.z, a1v.w};
#pragma unroll
            for (int i = 0; i < 8; i++) {
                acc[i][0] += av[i] * bv.x;
                acc[i][1] += av[i] * bv.y;
                acc[i][2] += av[i] * bv.z;
                acc[i][3] += av[i] * bv.w;
            }
        }
    }
    float* Cw = blockIdx.z ? g_pB : g_pA;
#pragma unroll
    for (int i = 0; i < 8; i++) {
        float4 v = make_float4(acc[i][0], acc[i][1], acc[i][2], acc[i][3]);
        *(float4*)(Cw + (size_t)(m0 + tr * 8 + i) * NH3 + n0 + tc * 4) = v;
    }
}

// ---------------- tree elementwise step ----------------
__global__ void tree_elem_kernel(int k) {
    int idx = blockIdx.x * 256 + threadIdx.x;   // 262144
    int s = idx >> 8, i = idx & 255;
    size_t pb = (size_t)(s * 63 + k) * NH3;
    size_t ab = (size_t)s * NH3;
    float t0 = g_pre[pb + i]       + g_pA[ab + i]       + g_pB[ab + i];
    float t1 = g_pre[pb + 256 + i] + g_pA[ab + 256 + i] + g_pB[ab + 256 + i];
    float t2 = g_pre[pb + 512 + i] + g_pA[ab + 512 + i] + g_pB[ab + 512 + i];
    float hc = g_h[idx];
    float f = sigf(t0) * hc;
    g_h[idx] = tanhf(sigf(t1) * tanhf(t2) + f);
}

// ---------------- gi = sv @ wih^T + bih (combine k-split halves) ----------------
__global__ void gi_combine_kernel(const float* __restrict__ bih) {
    int idx = blockIdx.x * 256 + threadIdx.x;   // 786432
    int n = idx % NH3;
    g_gi[idx] = g_pA[idx] + g_pB[idx] + bih[n];
}

// ---------------- GRU: 8-CTA cluster, whh register-resident, DSMEM gh reads ----------------
__device__ __forceinline__ uint32_t smem_u32(const void* p) {
    return (uint32_t)__cvta_generic_to_shared(p);
}
__device__ __forceinline__ uint32_t mapa_u32(uint32_t a, uint32_t r) {
    uint32_t o;
    asm("mapa.shared::cluster.u32 %0, %1, %2;" : "=r"(o) : "r"(a), "r"(r));
    return o;
}
__device__ __forceinline__ float ld_remote(uint32_t a) {
    float v;
    asm volatile("ld.shared::cluster.f32 %0, [%1];" : "=f"(v) : "r"(a) : "memory");
    return v;
}
__device__ __forceinline__ void cluster_barrier() {
    asm volatile("barrier.cluster.arrive.aligned;" ::: "memory");
    asm volatile("barrier.cluster.wait.aligned;" ::: "memory");
}

__global__ void __cluster_dims__(8, 1, 1) __launch_bounds__(256, 1)
gru_kernel(const float* __restrict__ whh, const float* __restrict__ bhh,
           const float* __restrict__ h0) {
    __shared__ float hsh[H];
    __shared__ float ghsh[2][96];

    int tid = threadIdx.x;
    unsigned rank;
    asm("mov.u32 %0, %%cluster_ctarank;" : "=r"(rank));
    int g = tid >> 3, p = tid & 7;
    int jbase = (int)rank * 96 + g * 3;   // 3 output rows owned by this thread-group

    // whh slice in registers: 3 outputs x 32 k-values (k = p*32 + u)
    float w[3][32], bh[3];
#pragma unroll
    for (int c = 0; c < 3; c++) {
        int j = jbase + c;
        bh[c] = bhh[j];
        const float4* wr = (const float4*)(whh + (size_t)j * H + p * 32);
#pragma unroll
        for (int u = 0; u < 8; u++) {
            float4 v = wr[u];
            w[c][4 * u] = v.x; w[c][4 * u + 1] = v.y;
            w[c][4 * u + 2] = v.z; w[c][4 * u + 3] = v.w;
        }
    }
    hsh[tid] = h0[tid];

    // remote gather addresses for gh[c*256 + tid] (owner = j/96, offset = j%96)
    uint32_t radr[2][3];
#pragma unroll
    for (int par = 0; par < 2; par++)
#pragma unroll
        for (int c = 0; c < 3; c++) {
            int j = c * H + tid;
            radr[par][c] = mapa_u32(smem_u32(&ghsh[par][j % 96]), (uint32_t)(j / 96));
        }

    for (int t = 0; t < S_SENT; t++) {
        __syncthreads();                 // hsh from previous step visible
        int par = t & 1;
        const float* gir = g_gi + (size_t)t * NH3;
        float gi0 = __ldg(gir + tid), gi1 = __ldg(gir + 256 + tid), gi2 = __ldg(gir + 512 + tid);

        float hv[32];
        const float4* hp = (const float4*)(hsh + p * 32);
#pragma unroll
        for (int u = 0; u < 8; u++) {
            float4 v = hp[u];
            hv[4 * u] = v.x; hv[4 * u + 1] = v.y;
            hv[4 * u + 2] = v.z; hv[4 * u + 3] = v.w;
        }
        float a0 = 0.f, a1 = 0.f, a2 = 0.f;
#pragma unroll
        for (int u = 0; u < 32; u++) {
            a0 += w[0][u] * hv[u];
            a1 += w[1][u] * hv[u];
            a2 += w[2][u] * hv[u];
        }
#pragma unroll
        for (int off = 4; off > 0; off >>= 1) {
            a0 += __shfl_down_sync(0xffffffffu, a0, off, 8);
            a1 += __shfl_down_sync(0xffffffffu, a1, off, 8);
            a2 += __shfl_down_sync(0xffffffffu, a2, off, 8);
        }
        if (p == 0) {
            ghsh[par][g * 3 + 0] = a0 + bh[0];
            ghsh[par][g * 3 + 1] = a1 + bh[1];
            ghsh[par][g * 3 + 2] = a2 + bh[2];
        }
        cluster_barrier();               // gh ready cluster-wide

        float gh0 = ld_remote(radr[par][0]);
        float gh1 = ld_remote(radr[par][1]);
        float gh2 = ld_remote(radr[par][2]);
        float hh = hsh[tid];
        float r = sigf(gi0 + gh0);
        float z = sigf(gi1 + gh1);
        float n = tanhf(gi2 + r * gh2);
        hsh[tid] = (1.0f - z) * n + z * hh;
    }
    __syncthreads();
    if (rank == 0) g_hT[tid] = hsh[tid];
}

// ---------------- topic vector, gate fusion, classifier, softmax ----------------
__global__ void final_kernel(const float* __restrict__ DT,
                             const float* __restrict__ gate_W, const float* __restrict__ gate_U,
                             const float* __restrict__ gate_b,
                             const float* __restrict__ mlp_W, const float* __restrict__ mlp_b,
                             const float* __restrict__ out_W, const float* __restrict__ out_b,
                             float* __restrict__ out) {
    __shared__ float tsh[H], hsh[H], vsh[H], lg[NTGT];
    int tid = threadIdx.x;   // 256 threads
    float acc = mlp_b[tid];
    const float* mr = mlp_W + (size_t)tid * NTOPIC;
#pragma unroll 4
    for (int k = 0; k < NTOPIC; k++) acc += mr[k] * DT[k];
    tsh[tid] = tanhf(acc);
    hsh[tid] = g_hT[tid];
    __syncthreads();
    float ga = gate_b[tid], gb = gate_b[tid + H];
    const float* wr = gate_W + (size_t)tid * H;
    const float* wr2 = gate_W + (size_t)(tid + H) * H;
    const float* ur = gate_U + (size_t)tid * H;
    const float* ur2 = gate_U + (size_t)(tid + H) * H;
#pragma unroll 4
    for (int k = 0; k < H; k++) {
        float hk = hsh[k], tk = tsh[k];
        ga += wr[k] * hk + ur[k] * tk;
        gb += wr2[k] * hk + ur2[k] * tk;
    }
    vsh[tid] = tanhf(sigf(ga) * hsh[tid] + sigf(gb) * tsh[tid]);
    __syncthreads();
    int wix = tid >> 5, lane = tid & 31;
    if (wix < NTGT) {
        float a = 0.f;
        for (int k = lane; k < H; k += 32) a += out_W[wix * H + k] * vsh[k];
#pragma unroll
        for (int off = 16; off > 0; off >>= 1) a += __shfl_down_sync(0xffffffffu, a, off);
        if (lane == 0) lg[wix] = a + out_b[wix];
    }
    __syncthreads();
    if (tid == 0) {
        float mx = lg[0];
        for (int i = 1; i < NTGT; i++) mx = fmaxf(mx, lg[i]);
        float s = 0.f, e[NTGT];
        for (int i = 0; i < NTGT; i++) { e[i] = expf(lg[i] - mx); s += e[i]; }
        for (int i = 0; i < NTGT; i++) out[i] = e[i] / s;
    }
}

extern "C" void kernel_launch(void* const* d_in, const int* in_sizes, int n_in,
                              void* d_out, int out_size) {
    const int*   sidx    = (const int*)  d_in[0];
    const int*   dep     = (const int*)  d_in[1];
    const float* DT      = (const float*)d_in[2];
    const float* h0      = (const float*)d_in[3];
    const float* idx2vec = (const float*)d_in[4];
    const float* q       = (const float*)d_in[5];
    const float* W       = (const float*)d_in[6];
    const float* U       = (const float*)d_in[7];
    const float* D       = (const float*)d_in[8];
    const float* b       = (const float*)d_in[9];
    const float* gru_wih = (const float*)d_in[10];
    const float* gru_whh = (const float*)d_in[11];
    const float* gru_bih = (const float*)d_in[12];
    const float* gru_bhh = (const float*)d_in[13];
    const float* gate_W  = (const float*)d_in[14];
    const float* gate_U  = (const float*)d_in[15];
    const float* gate_b  = (const float*)d_in[16];
    const float* mlp_W   = (const float*)d_in[17];
    const float* mlp_b   = (const float*)d_in[18];
    const float* out_W   = (const float*)d_in[19];
    const float* out_b   = (const float*)d_in[20];
    float* out = (float*)d_out;

    prep_kernel<<<10, NH3>>>(D, q);
    wx_kernel<<<dim3(6, 512), 256>>>(sidx, dep, idx2vec, W, b);
    leaf_kernel<<<1024, 256>>>();

    for (int k = L_W - 2; k >= 0; k--) {
        ab_gemm<<<dim3(12, 8, 2), 256>>>(U);
        tree_elem_kernel<<<1024, 256>>>(k);
    }

    ab_gemm<<<dim3(12, 8, 2), 256>>>(gru_wih);
    gi_combine_kernel<<<3072, 256>>>(gru_bih);

    gru_kernel<<<8, 256>>>(gru_whh, gru_bhh, h0);

    final_kernel<<<1, 256>>>(DT, gate_W, gate_U, gate_b, mlp_W, mlp_b, out_W, out_b, out);
}